// round 1
// baseline (speedup 1.0000x reference)
#include <cuda_runtime.h>
#include <math.h>

// Problem constants
#define B    64
#define T    512
#define VSZ  32000
#define EMB  512
#define HID  1024
#define ENC  1024
#define NROW (B*T)        // 32768
#define GATES4 (4*HID)    // 4096
#define FCK  (HID+ENC+EMB) // 2560

// Scratch (no cudaMalloc allowed)
__device__ float g_e[B*EMB];          // embeddings [64,512]
__device__ float g_hW[B*HID];         // h0 @ W_h^T + attn_b  [64,1024]
__device__ float g_scores[B*T];       // scores -> softmax weights [64,512]
__device__ float g_ctx[B*ENC];        // context [64,1024]
__device__ float g_gates[B*GATES4];   // LSTM gates pre-activation [64,4096]

// ---------------------------------------------------------------------------
// init: pred = fc_b broadcast, hW = attn_b broadcast, scores/gates/ctx = 0
// ---------------------------------------------------------------------------
__global__ void init_kernel(float* __restrict__ pred, const float* __restrict__ fc_b,
                            const float* __restrict__ attn_b) {
    int i = blockIdx.x * blockDim.x + threadIdx.x;
    int stride = gridDim.x * blockDim.x;
    for (int idx = i; idx < B*VSZ; idx += stride) pred[idx] = fc_b[idx % VSZ];
    for (int idx = i; idx < B*HID; idx += stride) g_hW[idx] = attn_b[idx & (HID-1)];
    for (int idx = i; idx < B*T;   idx += stride) g_scores[idx] = 0.f;
    for (int idx = i; idx < B*GATES4; idx += stride) g_gates[idx] = 0.f;
    for (int idx = i; idx < B*ENC; idx += stride) g_ctx[idx] = 0.f;
}

// ---------------------------------------------------------------------------
// embedding gather
// ---------------------------------------------------------------------------
__global__ void embed_kernel(const int* __restrict__ tok,
                             const float* __restrict__ emb) {
    int b = blockIdx.x;
    long r = (long)tok[b];
    for (int i = threadIdx.x; i < EMB; i += blockDim.x)
        g_e[b*EMB + i] = emb[r*EMB + i];
}

// ---------------------------------------------------------------------------
// Generic small-M GEMM: C[m,n] += sum_k A[m*lda+k] * B[n*ldb+k]
// M = 64 fixed, tile N=64, 256 threads (16x16), 4x4 per thread.
// grid.x = N/64, grid.y = k-splits (accumulate via atomics)
// ---------------------------------------------------------------------------
__global__ void gemm_acc(const float* __restrict__ A, int lda,
                         const float* __restrict__ Bm, int ldb,
                         float* __restrict__ C, int ldc, int K) {
    __shared__ float As[16][68];
    __shared__ float Bs[16][68];
    int tid = threadIdx.x;
    int nBase = blockIdx.x * 64;
    int kchunk = K / gridDim.y;
    int k0 = blockIdx.y * kchunk;
    int kend = k0 + kchunk;
    int tx = tid & 15, ty = tid >> 4;
    int lrow = tid >> 2;          // 0..63
    int lcol = (tid & 3) * 4;     // 0,4,8,12
    float acc[4][4];
    #pragma unroll
    for (int m = 0; m < 4; m++)
        #pragma unroll
        for (int n = 0; n < 4; n++) acc[m][n] = 0.f;

    for (int k = k0; k < kend; k += 16) {
        float4 av = *(const float4*)(A + (size_t)lrow*lda + k + lcol);
        float4 bv = *(const float4*)(Bm + (size_t)(nBase + lrow)*ldb + k + lcol);
        __syncthreads();
        As[lcol+0][lrow] = av.x; As[lcol+1][lrow] = av.y;
        As[lcol+2][lrow] = av.z; As[lcol+3][lrow] = av.w;
        Bs[lcol+0][lrow] = bv.x; Bs[lcol+1][lrow] = bv.y;
        Bs[lcol+2][lrow] = bv.z; Bs[lcol+3][lrow] = bv.w;
        __syncthreads();
        #pragma unroll
        for (int kk = 0; kk < 16; kk++) {
            float af[4], bf[4];
            *(float4*)af = *(const float4*)&As[kk][ty*4];
            *(float4*)bf = *(const float4*)&Bs[kk][tx*4];
            #pragma unroll
            for (int m = 0; m < 4; m++)
                #pragma unroll
                for (int n = 0; n < 4; n++)
                    acc[m][n] = fmaf(af[m], bf[n], acc[m][n]);
        }
    }
    #pragma unroll
    for (int m = 0; m < 4; m++)
        #pragma unroll
        for (int n = 0; n < 4; n++)
            atomicAdd(&C[(size_t)(ty*4+m)*ldc + nBase + tx*4 + n], acc[m][n]);
}

// ---------------------------------------------------------------------------
// Attention score kernel: the big GEMM, fused epilogue.
// scores[r] += sum_j v[j] * tanh( hW[b,j] + sum_k enc[r,k]*attn_W[j,1024+k] )
// rows r = b*512 + t (32768), j over 1024.
// Tile: 128 rows x 128 j, 256 threads (16x16), 8x8 per thread, k-chunks of 16.
// grid = (256 row-tiles, 8 j-tiles)
// ---------------------------------------------------------------------------
__global__ void score_kernel(const float* __restrict__ enc,
                             const float* __restrict__ W,   // attn_W
                             const float* __restrict__ v) {
    __shared__ float As[16][132];
    __shared__ float Bs[16][132];
    int tid = threadIdx.x;
    int rowBase = blockIdx.x * 128;
    int jBase   = blockIdx.y * 128;
    int b = rowBase >> 9;                   // /512, tile lies in one b
    int tx = tid & 15, ty = tid >> 4;
    int arow = tid >> 1;                    // 0..127
    int acol0 = (tid & 1) * 8;              // 0 or 8

    const float* Abase = enc + (size_t)rowBase * ENC;
    const float* Bbase = W + HID;           // enc-part columns of attn_W

    float acc[8][8];
    #pragma unroll
    for (int m = 0; m < 8; m++)
        #pragma unroll
        for (int n = 0; n < 8; n++) acc[m][n] = 0.f;

    for (int k0 = 0; k0 < ENC; k0 += 16) {
        float4 a0 = *(const float4*)(Abase + (size_t)arow*ENC + k0 + acol0);
        float4 a1 = *(const float4*)(Abase + (size_t)arow*ENC + k0 + acol0 + 4);
        float4 b0 = *(const float4*)(Bbase + (size_t)(jBase+arow)*(ENC+HID) + k0 + acol0);
        float4 b1 = *(const float4*)(Bbase + (size_t)(jBase+arow)*(ENC+HID) + k0 + acol0 + 4);
        __syncthreads();
        As[acol0+0][arow]=a0.x; As[acol0+1][arow]=a0.y; As[acol0+2][arow]=a0.z; As[acol0+3][arow]=a0.w;
        As[acol0+4][arow]=a1.x; As[acol0+5][arow]=a1.y; As[acol0+6][arow]=a1.z; As[acol0+7][arow]=a1.w;
        Bs[acol0+0][arow]=b0.x; Bs[acol0+1][arow]=b0.y; Bs[acol0+2][arow]=b0.z; Bs[acol0+3][arow]=b0.w;
        Bs[acol0+4][arow]=b1.x; Bs[acol0+5][arow]=b1.y; Bs[acol0+6][arow]=b1.z; Bs[acol0+7][arow]=b1.w;
        __syncthreads();
        #pragma unroll
        for (int kk = 0; kk < 16; kk++) {
            float af[8], bf[8];
            *(float4*)(af+0) = *(const float4*)&As[kk][ty*8];
            *(float4*)(af+4) = *(const float4*)&As[kk][ty*8+4];
            *(float4*)(bf+0) = *(const float4*)&Bs[kk][tx*8];
            *(float4*)(bf+4) = *(const float4*)&Bs[kk][tx*8+4];
            #pragma unroll
            for (int m = 0; m < 8; m++)
                #pragma unroll
                for (int n = 0; n < 8; n++)
                    acc[m][n] = fmaf(af[m], bf[n], acc[m][n]);
        }
    }

    // epilogue: tanh + v-weighted reduction over j within tile
    float hw[8], vv[8];
    #pragma unroll
    for (int n = 0; n < 8; n++) {
        hw[n] = g_hW[b*HID + jBase + tx*8 + n];
        vv[n] = v[jBase + tx*8 + n];
    }
    #pragma unroll
    for (int m = 0; m < 8; m++) {
        float s = 0.f;
        #pragma unroll
        for (int n = 0; n < 8; n++)
            s += vv[n] * tanhf(acc[m][n] + hw[n]);
        // reduce over 16 lanes sharing the same ty (consecutive lanes)
        #pragma unroll
        for (int off = 8; off > 0; off >>= 1)
            s += __shfl_down_sync(0xffffffffu, s, off, 16);
        if (tx == 0)
            atomicAdd(&g_scores[rowBase + ty*8 + m], s);
    }
}

// ---------------------------------------------------------------------------
// softmax over T=512 per batch row (in place on g_scores)
// ---------------------------------------------------------------------------
__global__ void softmax_kernel() {
    int b = blockIdx.x;
    int t = threadIdx.x;            // 512
    __shared__ float red[512];
    float s = g_scores[b*T + t];
    red[t] = s; __syncthreads();
    for (int off = 256; off > 0; off >>= 1) {
        if (t < off) red[t] = fmaxf(red[t], red[t+off]);
        __syncthreads();
    }
    float mx = red[0];
    __syncthreads();
    float e = expf(s - mx);
    red[t] = e; __syncthreads();
    for (int off = 256; off > 0; off >>= 1) {
        if (t < off) red[t] += red[t+off];
        __syncthreads();
    }
    g_scores[b*T + t] = e / red[0];
}

// ---------------------------------------------------------------------------
// ctx[b,e] = sum_t w[b,t] * enc[b,t,e]   grid (64, 4 t-splits)
// ---------------------------------------------------------------------------
__global__ void ctx_kernel(const float* __restrict__ enc) {
    int b = blockIdx.x;
    int tchunk = T / gridDim.y;
    int t0 = blockIdx.y * tchunk;
    __shared__ float ws[512];
    for (int i = threadIdx.x; i < tchunk; i += blockDim.x)
        ws[i] = g_scores[b*T + t0 + i];
    __syncthreads();
    float acc[4] = {0.f, 0.f, 0.f, 0.f};
    const float* eb = enc + (size_t)b*T*ENC + (size_t)t0*ENC;
    for (int t = 0; t < tchunk; t++) {
        float wt = ws[t];
        #pragma unroll
        for (int q = 0; q < 4; q++)
            acc[q] = fmaf(wt, eb[(size_t)t*ENC + threadIdx.x + q*256], acc[q]);
    }
    #pragma unroll
    for (int q = 0; q < 4; q++)
        atomicAdd(&g_ctx[b*ENC + threadIdx.x + q*256], acc[q]);
}

// ---------------------------------------------------------------------------
// LSTM pointwise: gates + biases -> h_new, c_new (written straight to d_out)
// ---------------------------------------------------------------------------
__global__ void lstm_kernel(const float* __restrict__ b_ih,
                            const float* __restrict__ b_hh,
                            const float* __restrict__ c0,
                            float* __restrict__ h_new,
                            float* __restrict__ c_new) {
    int idx = blockIdx.x * blockDim.x + threadIdx.x;   // 65536
    int b = idx >> 10, j = idx & 1023;
    const float* g4 = g_gates + b*GATES4;
    float ig = g4[j]        + b_ih[j]        + b_hh[j];
    float fg = g4[HID+j]    + b_ih[HID+j]    + b_hh[HID+j];
    float gg = g4[2*HID+j]  + b_ih[2*HID+j]  + b_hh[2*HID+j];
    float og = g4[3*HID+j]  + b_ih[3*HID+j]  + b_hh[3*HID+j];
    ig = 1.f/(1.f+expf(-ig));
    fg = 1.f/(1.f+expf(-fg));
    og = 1.f/(1.f+expf(-og));
    gg = tanhf(gg);
    float c = fg * c0[idx] + ig * gg;
    float h = og * tanhf(c);
    c_new[idx] = c;
    h_new[idx] = h;
}

// ---------------------------------------------------------------------------
extern "C" void kernel_launch(void* const* d_in, const int* in_sizes, int n_in,
                              void* d_out, int out_size) {
    const int*   tok     = (const int*)  d_in[0];
    const float* h0      = (const float*)d_in[1];
    const float* c0      = (const float*)d_in[2];
    const float* enc     = (const float*)d_in[3];
    const float* emb     = (const float*)d_in[4];
    const float* attn_W  = (const float*)d_in[5];
    const float* attn_b  = (const float*)d_in[6];
    const float* v_W     = (const float*)d_in[7];
    const float* W_ih    = (const float*)d_in[8];
    const float* W_hh    = (const float*)d_in[9];
    const float* b_ih    = (const float*)d_in[10];
    const float* b_hh    = (const float*)d_in[11];
    const float* fc_W    = (const float*)d_in[12];
    const float* fc_b    = (const float*)d_in[13];

    float* pred  = (float*)d_out;                       // [64, 32000]
    float* h_new = pred + (size_t)B*VSZ;                // [1,64,1024]
    float* c_new = h_new + (size_t)B*HID;               // [1,64,1024]

    float *d_e, *d_hW, *d_ctx, *d_gates;
    cudaGetSymbolAddress((void**)&d_e,     g_e);
    cudaGetSymbolAddress((void**)&d_hW,    g_hW);
    cudaGetSymbolAddress((void**)&d_ctx,   g_ctx);
    cudaGetSymbolAddress((void**)&d_gates, g_gates);

    // 1. init (bias broadcasts + zeroing)
    init_kernel<<<2048, 256>>>(pred, fc_b, attn_b);

    // 2. embedding gather
    embed_kernel<<<B, 256>>>(tok, emb);

    // 3. hW += h0 @ attn_W[:, :HID]^T     (small GEMM, k-split 8)
    gemm_acc<<<dim3(HID/64, 8), 256>>>(h0, HID, attn_W, ENC+HID, d_hW, HID, HID);

    // 4. attention scores (the big fused GEMM)
    score_kernel<<<dim3(NROW/128, HID/128), 256>>>(enc, attn_W, v_W);

    // 5. softmax over T
    softmax_kernel<<<B, T>>>();

    // 6. ctx weighted sum (t-split 4)
    ctx_kernel<<<dim3(B, 4), 256>>>(enc);

    // 7-9. gates += e@W_ih[:, :512]^T + ctx@W_ih[:, 512:]^T + h0@W_hh^T
    gemm_acc<<<dim3(GATES4/64, 4), 256>>>(d_e,   EMB, W_ih,       EMB+ENC, d_gates, GATES4, EMB);
    gemm_acc<<<dim3(GATES4/64, 4), 256>>>(d_ctx, ENC, W_ih + EMB, EMB+ENC, d_gates, GATES4, ENC);
    gemm_acc<<<dim3(GATES4/64, 4), 256>>>(h0,    HID, W_hh,       HID,     d_gates, GATES4, HID);

    // 10. LSTM pointwise -> h_new, c_new in d_out
    lstm_kernel<<<(B*HID)/256, 256>>>(b_ih, b_hh, c0, h_new, c_new);

    // 11-13. pred += h_new@fc_W[:, :1024]^T + ctx@fc_W[:,1024:2048]^T + e@fc_W[:,2048:]^T
    gemm_acc<<<dim3(VSZ/64, 1), 256>>>(h_new, HID, fc_W,            FCK, pred, VSZ, HID);
    gemm_acc<<<dim3(VSZ/64, 1), 256>>>(d_ctx, ENC, fc_W + HID,      FCK, pred, VSZ, ENC);
    gemm_acc<<<dim3(VSZ/64, 1), 256>>>(d_e,   EMB, fc_W + HID+ENC,  FCK, pred, VSZ, EMB);
}

// round 3
// speedup vs baseline: 1.9388x; 1.9388x over previous
#include <cuda_runtime.h>
#include <cuda_bf16.h>
#include <math.h>
#include <stdint.h>

// Problem constants
#define B    64
#define T    512
#define VSZ  32000
#define EMB  512
#define HID  1024
#define ENC  1024
#define NROW (B*T)        // 32768
#define GATES4 (4*HID)    // 4096
#define FCK  (HID+ENC+EMB) // 2560

// Scratch (no cudaMalloc allowed)
__device__ float g_e[B*EMB];
__device__ float g_hW[B*HID];
__device__ float g_scores[B*T];
__device__ float g_ctx[B*ENC];
__device__ float g_gates[B*GATES4];

// bf16 hi/lo split operands for the tensor-core attention GEMM
__device__ __nv_bfloat16 g_enc_hi[NROW*ENC];   // 64MB
__device__ __nv_bfloat16 g_enc_lo[NROW*ENC];   // 64MB
__device__ __nv_bfloat16 g_Wh[HID*ENC];        // 2MB
__device__ __nv_bfloat16 g_Wl[HID*ENC];        // 2MB

// ---------------------------------------------------------------------------
// helpers
// ---------------------------------------------------------------------------
__device__ __forceinline__ uint32_t smem_u32(const void* p) {
    uint32_t a;
    asm("{ .reg .u64 t; cvta.to.shared.u64 t, %1; cvt.u32.u64 %0, t; }" : "=r"(a) : "l"(p));
    return a;
}
__device__ __forceinline__ uint32_t swz128(uint32_t o) { return o ^ ((o >> 3) & 0x70u); }

__device__ __forceinline__ float tanh_fast(float x) {
    float e = __expf(2.f * x);
    return 1.f - __fdividef(2.f, e + 1.f);
}
__device__ __forceinline__ void cp16(uint32_t saddr, const void* gptr) {
    asm volatile("cp.async.cg.shared.global [%0], [%1], 16;"
                 :: "r"(saddr), "l"(__cvta_generic_to_global(gptr)) : "memory");
}
__device__ __forceinline__ void cp_commit() {
    asm volatile("cp.async.commit_group;" ::: "memory");
}
__device__ __forceinline__ void cp_wait1() {
    asm volatile("cp.async.wait_group 1;" ::: "memory");
}
__device__ __forceinline__ void cp_wait0() {
    asm volatile("cp.async.wait_group 0;" ::: "memory");
}
__device__ __forceinline__ void ldmx4(uint32_t* r, uint32_t addr) {
    asm volatile("ldmatrix.sync.aligned.m8n8.x4.shared.b16 {%0,%1,%2,%3}, [%4];"
                 : "=r"(r[0]), "=r"(r[1]), "=r"(r[2]), "=r"(r[3]) : "r"(addr));
}
__device__ __forceinline__ void mma16816(float* c, const uint32_t* a,
                                         uint32_t b0, uint32_t b1) {
    asm volatile(
        "mma.sync.aligned.m16n8k16.row.col.f32.bf16.bf16.f32 "
        "{%0,%1,%2,%3}, {%4,%5,%6,%7}, {%8,%9}, {%0,%1,%2,%3};"
        : "+f"(c[0]), "+f"(c[1]), "+f"(c[2]), "+f"(c[3])
        : "r"(a[0]), "r"(a[1]), "r"(a[2]), "r"(a[3]), "r"(b0), "r"(b1));
}

// ---------------------------------------------------------------------------
// init
// ---------------------------------------------------------------------------
__global__ void init_kernel(float* __restrict__ pred, const float* __restrict__ fc_b,
                            const float* __restrict__ attn_b) {
    int i = blockIdx.x * blockDim.x + threadIdx.x;
    int stride = gridDim.x * blockDim.x;
    for (int idx = i; idx < B*VSZ; idx += stride) pred[idx] = fc_b[idx % VSZ];
    for (int idx = i; idx < B*HID; idx += stride) g_hW[idx] = attn_b[idx & (HID-1)];
    for (int idx = i; idx < B*T;   idx += stride) g_scores[idx] = 0.f;
    for (int idx = i; idx < B*GATES4; idx += stride) g_gates[idx] = 0.f;
    for (int idx = i; idx < B*ENC; idx += stride) g_ctx[idx] = 0.f;
}

// ---------------------------------------------------------------------------
// embedding gather
// ---------------------------------------------------------------------------
__global__ void embed_kernel(const int* __restrict__ tok,
                             const float* __restrict__ emb) {
    int b = blockIdx.x;
    long r = (long)tok[b];
    for (int i = threadIdx.x; i < EMB; i += blockDim.x)
        g_e[b*EMB + i] = emb[r*EMB + i];
}

// ---------------------------------------------------------------------------
// bf16 hi/lo conversion kernels
// ---------------------------------------------------------------------------
__global__ void convert_enc_k(const float* __restrict__ enc) {
    int i = blockIdx.x * blockDim.x + threadIdx.x;
    int stride = gridDim.x * blockDim.x;
    const int n4 = (NROW*ENC) / 4;
    const float4* src = (const float4*)enc;
    ushort4* dhi = (ushort4*)g_enc_hi;
    ushort4* dlo = (ushort4*)g_enc_lo;
    for (int v = i; v < n4; v += stride) {
        float4 x = src[v];
        __nv_bfloat16 h0 = __float2bfloat16(x.x);
        __nv_bfloat16 h1 = __float2bfloat16(x.y);
        __nv_bfloat16 h2 = __float2bfloat16(x.z);
        __nv_bfloat16 h3 = __float2bfloat16(x.w);
        ushort4 ph, pl;
        ph.x = __bfloat16_as_ushort(h0); ph.y = __bfloat16_as_ushort(h1);
        ph.z = __bfloat16_as_ushort(h2); ph.w = __bfloat16_as_ushort(h3);
        pl.x = __bfloat16_as_ushort(__float2bfloat16(x.x - __bfloat162float(h0)));
        pl.y = __bfloat16_as_ushort(__float2bfloat16(x.y - __bfloat162float(h1)));
        pl.z = __bfloat16_as_ushort(__float2bfloat16(x.z - __bfloat162float(h2)));
        pl.w = __bfloat16_as_ushort(__float2bfloat16(x.w - __bfloat162float(h3)));
        dhi[v] = ph; dlo[v] = pl;
    }
}

__global__ void convert_W_k(const float* __restrict__ attn_W) {
    int i = blockIdx.x * blockDim.x + threadIdx.x;
    int e0 = i * 4;
    int row = e0 >> 10, col = e0 & 1023;
    const float4* src = (const float4*)(attn_W + (size_t)row*(ENC+HID) + HID + col);
    float4 x = *src;
    __nv_bfloat16 h0 = __float2bfloat16(x.x);
    __nv_bfloat16 h1 = __float2bfloat16(x.y);
    __nv_bfloat16 h2 = __float2bfloat16(x.z);
    __nv_bfloat16 h3 = __float2bfloat16(x.w);
    ushort4 ph, pl;
    ph.x = __bfloat16_as_ushort(h0); ph.y = __bfloat16_as_ushort(h1);
    ph.z = __bfloat16_as_ushort(h2); ph.w = __bfloat16_as_ushort(h3);
    pl.x = __bfloat16_as_ushort(__float2bfloat16(x.x - __bfloat162float(h0)));
    pl.y = __bfloat16_as_ushort(__float2bfloat16(x.y - __bfloat162float(h1)));
    pl.z = __bfloat16_as_ushort(__float2bfloat16(x.z - __bfloat162float(h2)));
    pl.w = __bfloat16_as_ushort(__float2bfloat16(x.w - __bfloat162float(h3)));
    ((ushort4*)g_Wh)[i] = ph;
    ((ushort4*)g_Wl)[i] = pl;
}

// ---------------------------------------------------------------------------
// Generic small-M GEMM: C[m,n] += sum_k A[m*lda+k] * B[n*ldb+k]
// ---------------------------------------------------------------------------
__global__ void gemm_acc(const float* __restrict__ A, int lda,
                         const float* __restrict__ Bm, int ldb,
                         float* __restrict__ C, int ldc, int K) {
    __shared__ float As[16][68];
    __shared__ float Bs[16][68];
    int tid = threadIdx.x;
    int nBase = blockIdx.x * 64;
    int kchunk = K / gridDim.y;
    int k0 = blockIdx.y * kchunk;
    int kend = k0 + kchunk;
    int tx = tid & 15, ty = tid >> 4;
    int lrow = tid >> 2;
    int lcol = (tid & 3) * 4;
    float acc[4][4];
    #pragma unroll
    for (int m = 0; m < 4; m++)
        #pragma unroll
        for (int n = 0; n < 4; n++) acc[m][n] = 0.f;

    for (int k = k0; k < kend; k += 16) {
        float4 av = *(const float4*)(A + (size_t)lrow*lda + k + lcol);
        float4 bv = *(const float4*)(Bm + (size_t)(nBase + lrow)*ldb + k + lcol);
        __syncthreads();
        As[lcol+0][lrow] = av.x; As[lcol+1][lrow] = av.y;
        As[lcol+2][lrow] = av.z; As[lcol+3][lrow] = av.w;
        Bs[lcol+0][lrow] = bv.x; Bs[lcol+1][lrow] = bv.y;
        Bs[lcol+2][lrow] = bv.z; Bs[lcol+3][lrow] = bv.w;
        __syncthreads();
        #pragma unroll
        for (int kk = 0; kk < 16; kk++) {
            float af[4], bf[4];
            *(float4*)af = *(const float4*)&As[kk][ty*4];
            *(float4*)bf = *(const float4*)&Bs[kk][tx*4];
            #pragma unroll
            for (int m = 0; m < 4; m++)
                #pragma unroll
                for (int n = 0; n < 4; n++)
                    acc[m][n] = fmaf(af[m], bf[n], acc[m][n]);
        }
    }
    #pragma unroll
    for (int m = 0; m < 4; m++)
        #pragma unroll
        for (int n = 0; n < 4; n++)
            atomicAdd(&C[(size_t)(ty*4+m)*ldc + nBase + tx*4 + n], acc[m][n]);
}

// ---------------------------------------------------------------------------
// Attention score kernel via warp-level mma.sync (bf16 HMMA, hi/lo 3-pass).
// CTA: 256 rows x 128 j, 512 threads = 16 warps (4x4), warp tile 64x32.
// K pipeline: 48 chunks of 64 bf16 (3 passes x 1024), cp.async double buffer.
// Epilogue: scores[r] += sum_j v[j]*tanh(D[r,j] + hW[b,j])
// ---------------------------------------------------------------------------
#define MT 256
#define NT 128
#define KCH 64
#define ITERS 48
#define STG_A 32768                   // 256 rows * 128B
#define STG_B 16384                   // 128 rows * 128B
#define STG   (STG_A + STG_B)         // 49152
#define SCORE_SMEM (2 * STG)          // 98304

__global__ void __launch_bounds__(512, 1)
score_mma_kernel(const float* __restrict__ v_W) {
    extern __shared__ char smem[];
    const uint32_t sb = smem_u32(smem);
    const int tid = threadIdx.x;
    const int lane = tid & 31, wid = tid >> 5;
    const int m0 = (wid >> 2) * 64;       // warp row offset in CTA tile
    const int n0 = (wid & 3) * 32;        // warp col offset
    const int rowBase = blockIdx.x * MT;
    const int jBase   = blockIdx.y * NT;
    const int b = rowBase >> 9;

    float acc[4][4][4];
    #pragma unroll
    for (int mf = 0; mf < 4; mf++)
        #pragma unroll
        for (int nf = 0; nf < 4; nf++)
            #pragma unroll
            for (int q = 0; q < 4; q++) acc[mf][nf][q] = 0.f;

    // per-thread load coordinates (A: 4 vectors, B: 2 vectors of 16B)
    // idx = tid + t*512 ; row = idx>>3 ; c16 = idx&7
    #define ISSUE_LOAD(IT) do {                                                 \
        int p_ = (IT) >> 4;                                                     \
        int k0_ = ((IT) & 15) * KCH;                                            \
        const __nv_bfloat16* As_ = (p_ < 2) ? g_enc_hi : g_enc_lo;              \
        const __nv_bfloat16* Bs_ = (p_ == 1) ? g_Wl : g_Wh;                     \
        uint32_t aO_ = sb + ((IT) & 1) * STG;                                   \
        uint32_t bO_ = aO_ + STG_A;                                             \
        _Pragma("unroll")                                                       \
        for (int t_ = 0; t_ < 4; ++t_) {                                        \
            int idx_ = tid + t_ * 512;                                          \
            int r_ = idx_ >> 3, c_ = idx_ & 7;                                  \
            cp16(aO_ + swz128(r_ * 128 + c_ * 16),                              \
                 As_ + ((size_t)(rowBase + r_) << 10) + k0_ + (c_ << 3));       \
        }                                                                       \
        _Pragma("unroll")                                                       \
        for (int t_ = 0; t_ < 2; ++t_) {                                        \
            int idx_ = tid + t_ * 512;                                          \
            int r_ = idx_ >> 3, c_ = idx_ & 7;                                  \
            cp16(bO_ + swz128(r_ * 128 + c_ * 16),                              \
                 Bs_ + ((size_t)(jBase + r_) << 10) + k0_ + (c_ << 3));         \
        }                                                                       \
        cp_commit();                                                            \
    } while (0)

    ISSUE_LOAD(0);
    #pragma unroll 1
    for (int it = 0; it < ITERS; ++it) {
        if (it + 1 < ITERS) { ISSUE_LOAD(it + 1); cp_wait1(); }
        else                { cp_wait0(); }
        __syncthreads();
        uint32_t aO = sb + (it & 1) * STG;
        uint32_t bO = aO + STG_A;
        #pragma unroll
        for (int s = 0; s < 4; ++s) {
            uint32_t a[4][4];
            #pragma unroll
            for (int mf = 0; mf < 4; ++mf) {
                uint32_t addr = aO + swz128((m0 + mf*16 + (lane & 15)) * 128
                                            + ((lane >> 4) << 4) + s * 32);
                ldmx4(a[mf], addr);
            }
            uint32_t bf[2][4];
            #pragma unroll
            for (int bp = 0; bp < 2; ++bp) {
                int nrow = n0 + bp*16 + ((lane >> 4) << 3) + (lane & 7);
                uint32_t addr = bO + swz128(nrow * 128
                                            + (((lane >> 3) & 1) << 4) + s * 32);
                ldmx4(bf[bp], addr);
            }
            #pragma unroll
            for (int mf = 0; mf < 4; ++mf) {
                #pragma unroll
                for (int nf = 0; nf < 4; ++nf)
                    mma16816(acc[mf][nf], a[mf],
                             bf[nf >> 1][(nf & 1) * 2],
                             bf[nf >> 1][(nf & 1) * 2 + 1]);
            }
        }
        __syncthreads();
    }

    // epilogue: stage v and hW slices (reuse stage-0 smem)
    float* vs = (float*)smem;
    float* hw = vs + NT;
    if (tid < NT) {
        vs[tid] = v_W[jBase + tid];
        hw[tid] = g_hW[b * HID + jBase + tid];
    }
    __syncthreads();

    int groupID = lane >> 2, tig = lane & 3;
    #pragma unroll
    for (int mf = 0; mf < 4; ++mf) {
        int rowA = m0 + mf * 16 + groupID;
        float sA = 0.f, sB = 0.f;
        #pragma unroll
        for (int nf = 0; nf < 4; ++nf) {
            int col = n0 + nf * 8 + tig * 2;
            float v0 = vs[col], v1 = vs[col + 1];
            float w0 = hw[col], w1 = hw[col + 1];
            sA += v0 * tanh_fast(acc[mf][nf][0] + w0);
            sA += v1 * tanh_fast(acc[mf][nf][1] + w1);
            sB += v0 * tanh_fast(acc[mf][nf][2] + w0);
            sB += v1 * tanh_fast(acc[mf][nf][3] + w1);
        }
        sA += __shfl_xor_sync(0xffffffffu, sA, 1);
        sA += __shfl_xor_sync(0xffffffffu, sA, 2);
        sB += __shfl_xor_sync(0xffffffffu, sB, 1);
        sB += __shfl_xor_sync(0xffffffffu, sB, 2);
        if (tig == 0) {
            atomicAdd(&g_scores[rowBase + rowA], sA);
            atomicAdd(&g_scores[rowBase + rowA + 8], sB);
        }
    }
}

// ---------------------------------------------------------------------------
// softmax over T=512 per batch row
// ---------------------------------------------------------------------------
__global__ void softmax_kernel() {
    int b = blockIdx.x;
    int t = threadIdx.x;
    __shared__ float red[512];
    float s = g_scores[b*T + t];
    red[t] = s; __syncthreads();
    for (int off = 256; off > 0; off >>= 1) {
        if (t < off) red[t] = fmaxf(red[t], red[t+off]);
        __syncthreads();
    }
    float mx = red[0];
    __syncthreads();
    float e = expf(s - mx);
    red[t] = e; __syncthreads();
    for (int off = 256; off > 0; off >>= 1) {
        if (t < off) red[t] += red[t+off];
        __syncthreads();
    }
    g_scores[b*T + t] = e / red[0];
}

// ---------------------------------------------------------------------------
// ctx[b,e] = sum_t w[b,t] * enc[b,t,e]
// ---------------------------------------------------------------------------
__global__ void ctx_kernel(const float* __restrict__ enc) {
    int b = blockIdx.x;
    int tchunk = T / gridDim.y;
    int t0 = blockIdx.y * tchunk;
    __shared__ float ws[512];
    for (int i = threadIdx.x; i < tchunk; i += blockDim.x)
        ws[i] = g_scores[b*T + t0 + i];
    __syncthreads();
    float acc[4] = {0.f, 0.f, 0.f, 0.f};
    const float* eb = enc + (size_t)b*T*ENC + (size_t)t0*ENC;
    for (int t = 0; t < tchunk; t++) {
        float wt = ws[t];
        #pragma unroll
        for (int q = 0; q < 4; q++)
            acc[q] = fmaf(wt, eb[(size_t)t*ENC + threadIdx.x + q*256], acc[q]);
    }
    #pragma unroll
    for (int q = 0; q < 4; q++)
        atomicAdd(&g_ctx[b*ENC + threadIdx.x + q*256], acc[q]);
}

// ---------------------------------------------------------------------------
// LSTM pointwise
// ---------------------------------------------------------------------------
__global__ void lstm_kernel(const float* __restrict__ b_ih,
                            const float* __restrict__ b_hh,
                            const float* __restrict__ c0,
                            float* __restrict__ h_new,
                            float* __restrict__ c_new) {
    int idx = blockIdx.x * blockDim.x + threadIdx.x;
    int b = idx >> 10, j = idx & 1023;
    const float* g4 = g_gates + b*GATES4;
    float ig = g4[j]        + b_ih[j]        + b_hh[j];
    float fg = g4[HID+j]    + b_ih[HID+j]    + b_hh[HID+j];
    float gg = g4[2*HID+j]  + b_ih[2*HID+j]  + b_hh[2*HID+j];
    float og = g4[3*HID+j]  + b_ih[3*HID+j]  + b_hh[3*HID+j];
    ig = 1.f/(1.f+expf(-ig));
    fg = 1.f/(1.f+expf(-fg));
    og = 1.f/(1.f+expf(-og));
    gg = tanhf(gg);
    float c = fg * c0[idx] + ig * gg;
    float h = og * tanhf(c);
    c_new[idx] = c;
    h_new[idx] = h;
}

// ---------------------------------------------------------------------------
extern "C" void kernel_launch(void* const* d_in, const int* in_sizes, int n_in,
                              void* d_out, int out_size) {
    const int*   tok     = (const int*)  d_in[0];
    const float* h0      = (const float*)d_in[1];
    const float* c0      = (const float*)d_in[2];
    const float* enc     = (const float*)d_in[3];
    const float* emb     = (const float*)d_in[4];
    const float* attn_W  = (const float*)d_in[5];
    const float* attn_b  = (const float*)d_in[6];
    const float* v_W     = (const float*)d_in[7];
    const float* W_ih    = (const float*)d_in[8];
    const float* W_hh    = (const float*)d_in[9];
    const float* b_ih    = (const float*)d_in[10];
    const float* b_hh    = (const float*)d_in[11];
    const float* fc_W    = (const float*)d_in[12];
    const float* fc_b    = (const float*)d_in[13];

    float* pred  = (float*)d_out;                       // [64, 32000]
    float* h_new = pred + (size_t)B*VSZ;                // [1,64,1024]
    float* c_new = h_new + (size_t)B*HID;               // [1,64,1024]

    float *d_e, *d_ctx, *d_gates, *d_hW;
    cudaGetSymbolAddress((void**)&d_e,     g_e);
    cudaGetSymbolAddress((void**)&d_hW,    g_hW);
    cudaGetSymbolAddress((void**)&d_ctx,   g_ctx);
    cudaGetSymbolAddress((void**)&d_gates, g_gates);

    cudaFuncSetAttribute(score_mma_kernel,
                         cudaFuncAttributeMaxDynamicSharedMemorySize, SCORE_SMEM);

    // 1. init
    init_kernel<<<2048, 256>>>(pred, fc_b, attn_b);

    // 2. embedding gather
    embed_kernel<<<B, 256>>>(tok, emb);

    // 3. bf16 hi/lo conversions
    convert_enc_k<<<2048, 256>>>(enc);
    convert_W_k<<<1024, 256>>>(attn_W);

    // 4. hW += h0 @ attn_W[:, :HID]^T
    gemm_acc<<<dim3(HID/64, 8), 256>>>(h0, HID, attn_W, ENC+HID, d_hW, HID, HID);

    // 5. attention scores (HMMA mma.sync GEMM + fused epilogue)
    score_mma_kernel<<<dim3(NROW/MT, HID/NT), 512, SCORE_SMEM>>>(v_W);

    // 6. softmax over T
    softmax_kernel<<<B, T>>>();

    // 7. ctx weighted sum
    ctx_kernel<<<dim3(B, 4), 256>>>(enc);

    // 8-10. gates
    gemm_acc<<<dim3(GATES4/64, 4), 256>>>(d_e,   EMB, W_ih,       EMB+ENC, d_gates, GATES4, EMB);
    gemm_acc<<<dim3(GATES4/64, 4), 256>>>(d_ctx, ENC, W_ih + EMB, EMB+ENC, d_gates, GATES4, ENC);
    gemm_acc<<<dim3(GATES4/64, 4), 256>>>(h0,    HID, W_hh,       HID,     d_gates, GATES4, HID);

    // 11. LSTM pointwise
    lstm_kernel<<<(B*HID)/256, 256>>>(b_ih, b_hh, c0, h_new, c_new);

    // 12-14. vocab projection
    gemm_acc<<<dim3(VSZ/64, 1), 256>>>(h_new, HID, fc_W,            FCK, pred, VSZ, HID);
    gemm_acc<<<dim3(VSZ/64, 1), 256>>>(d_ctx, ENC, fc_W + HID,      FCK, pred, VSZ, ENC);
    gemm_acc<<<dim3(VSZ/64, 1), 256>>>(d_e,   EMB, fc_W + HID+ENC,  FCK, pred, VSZ, EMB);
}